// round 2
// baseline (speedup 1.0000x reference)
#include <cuda_runtime.h>
#include <cstdint>

// Problem constants: pred/target [8,3,512,512] fp32, output scalar fp32.
#define BATCH   8
#define CHAN    3
#define HW      262144              // 512*512
#define NB      16                  // coarse bins
#define NF      4096                // fine bins
#define NSLICE  48                  // 2 tensors * 8 * 3
#define SPLITS  20
#define CHUNK   13312               // ceil(HW/SPLITS) rounded to 1024

// Packed fine-bin statistic: bits[45:64) = count, bits[0:45) = sum(delta)*2^27,
// delta = x*4096 - j in [0,1). Worst case count = 262144 < 2^19, sumdelta*2^27 < 2^45.
#define CNT_SHIFT 45
#define DELTA_SCALE 134217728.0f    // 2^27
#define DELTA_INV   (1.0f/134217728.0f)

__device__ unsigned long long g_fine[NSLICE][NF];   // 1.5 MB scratch
__device__ unsigned char      g_maskbuf[BATCH * HW];// 2 MB mask bytes
__device__ float              g_w [NB][NF];         // w(c_j, k)
__device__ float              g_wp[NB][NF];         // dw/dx(c_j, k)

// ---------------------------------------------------------------------------
// Kernel 0: zero scratch + output, build Gaussian tables (65536 exps total).
// ---------------------------------------------------------------------------
__global__ void init_kernel(float* __restrict__ out) {
    int tid = blockIdx.x * blockDim.x + threadIdx.x;
    if (tid < NSLICE * NF) {
        ((unsigned long long*)g_fine)[tid] = 0ULL;
    }
    if (tid < NB * NF) {
        int k = tid / NF;
        int j = tid % NF;
        float ck = (float)k / 15.0f;                     // linspace(0,1,16)
        float cj = ((float)j + 0.5f) * (1.0f / (float)NF);
        float d  = cj - ck;
        float w  = expf(-d * d * 128.0f);                // inv_two_sigma2 = 128
        g_w [k][j] = w;
        g_wp[k][j] = -256.0f * d * w;
    }
    if (tid == 0) *out = 0.0f;
}

// ---------------------------------------------------------------------------
// Kernel 1: brightness mask from target.  mask = mean(target, ch) > 0.4
// ---------------------------------------------------------------------------
__global__ __launch_bounds__(256) void mask_kernel(const float* __restrict__ target) {
    int tid = blockIdx.x * blockDim.x + threadIdx.x;
    int p4  = tid * 4;
    if (p4 >= BATCH * HW) return;
    int b = p4 / HW;
    int r = p4 % HW;
    const float* base = target + (size_t)b * CHAN * HW + r;
    float4 t0 = *(const float4*)(base);
    float4 t1 = *(const float4*)(base + HW);
    float4 t2 = *(const float4*)(base + 2 * HW);
    uchar4 m;
    m.x = (unsigned char)(((t0.x + t1.x) + t2.x) / 3.0f > 0.4f);
    m.y = (unsigned char)(((t0.y + t1.y) + t2.y) / 3.0f > 0.4f);
    m.z = (unsigned char)(((t0.z + t1.z) + t2.z) / 3.0f > 0.4f);
    m.w = (unsigned char)(((t0.w + t1.w) + t2.w) / 3.0f > 0.4f);
    *(uchar4*)(g_maskbuf + p4) = m;
}

// ---------------------------------------------------------------------------
// Kernel 2: fine histogram.  One shared 64-bit atomic per masked pixel.
// grid = NSLICE * SPLITS blocks, 256 threads, 32 KB static smem.
// ---------------------------------------------------------------------------
__device__ __forceinline__ void fine_add(unsigned long long* sh, float x, unsigned char m) {
    if (m) {
        float tf = x * (float)NF;
        int j = (int)tf;
        j = min(max(j, 0), NF - 1);
        float dl = tf - (float)j;                        // exact in fp32, in [0,1)
        unsigned long long p = (1ULL << CNT_SHIFT)
                             | (unsigned long long)(unsigned)(dl * DELTA_SCALE);
        atomicAdd(&sh[j], p);
    }
}

__global__ __launch_bounds__(256) void hist_kernel(const float* __restrict__ pred,
                                                   const float* __restrict__ target) {
    __shared__ unsigned long long sh[NF];                // 32 KB
    int s     = blockIdx.x / SPLITS;                     // slice: tensor*24 + b*3 + c
    int chunk = blockIdx.x % SPLITS;
    int t  = s / 24;
    int bc = s % 24;
    int b  = bc / CHAN;

    for (int j = threadIdx.x; j < NF; j += 256) sh[j] = 0ULL;
    __syncthreads();

    const float* src = (t == 0 ? pred : target) + (size_t)bc * HW;
    const unsigned char* mk = g_maskbuf + (size_t)b * HW;

    int start = chunk * CHUNK;
    int end   = min(start + CHUNK, HW);
    for (int i = start + (int)threadIdx.x * 4; i < end; i += 256 * 4) {
        float4 x = *(const float4*)(src + i);
        uchar4 m = *(const uchar4*)(mk + i);
        fine_add(sh, x.x, m.x);
        fine_add(sh, x.y, m.y);
        fine_add(sh, x.z, m.z);
        fine_add(sh, x.w, m.w);
    }
    __syncthreads();

    unsigned long long* gf = g_fine[s];
    for (int j = threadIdx.x; j < NF; j += 256) {
        unsigned long long v = sh[j];
        if (v) atomicAdd(&gf[j], v);
    }
}

// ---------------------------------------------------------------------------
// Kernel 3: reconstruct 16-bin soft histograms (1st-order Taylor over fine
// bins), normalize, accumulate mean |pred_hist - target_hist|.
// grid = 24 blocks (one per b,c), 256 threads.
// ---------------------------------------------------------------------------
__global__ __launch_bounds__(256) void finish_kernel(float* __restrict__ out) {
    __shared__ float  sn [NF];                           // counts
    __shared__ float  sdv[NF];                           // sum(x - c_j)
    __shared__ double sh_hist[2][NB];

    int bc  = blockIdx.x;
    int tid = threadIdx.x;

    for (int t = 0; t < 2; t++) {
        const unsigned long long* gf = g_fine[t * 24 + bc];
        for (int j = tid; j < NF; j += 256) {
            unsigned long long v = gf[j];
            float n  = (float)(v >> CNT_SHIFT);
            float sd = (float)(v & ((1ULL << CNT_SHIFT) - 1)) * DELTA_INV;
            sn [j] = n;
            sdv[j] = (sd - 0.5f * n) * (1.0f / (float)NF); // sum(x_i) - n*c_j
        }
        __syncthreads();

        int k      = tid >> 4;                           // 16 threads per bin
        int lane16 = tid & 15;
        const float* wr  = g_w [k];
        const float* wpr = g_wp[k];
        double acc = 0.0;
        for (int j = lane16; j < NF; j += 16)
            acc += (double)sn[j] * (double)wr[j] + (double)sdv[j] * (double)wpr[j];
        #pragma unroll
        for (int off = 8; off > 0; off >>= 1)
            acc += __shfl_down_sync(0xffffffffu, acc, off, 16);
        if (lane16 == 0) sh_hist[t][k] = acc;
        __syncthreads();
    }

    if (tid == 0) {
        double s0 = 0.0, s1 = 0.0;
        for (int k = 0; k < NB; k++) { s0 += sh_hist[0][k]; s1 += sh_hist[1][k]; }
        double i0 = 1.0 / (s0 + 1e-7);
        double i1 = 1.0 / (s1 + 1e-7);
        double acc = 0.0;
        for (int k = 0; k < NB; k++)
            acc += fabs(sh_hist[0][k] * i0 - sh_hist[1][k] * i1);
        atomicAdd(out, (float)(acc * (1.0 / 384.0)));
    }
}

// ---------------------------------------------------------------------------
extern "C" void kernel_launch(void* const* d_in, const int* in_sizes, int n_in,
                              void* d_out, int out_size) {
    const float* pred   = (const float*)d_in[0];
    const float* target = (const float*)d_in[1];
    float* out = (float*)d_out;

    // init: cover max(NSLICE*NF, NB*NF) = 196608 threads
    init_kernel<<<(NSLICE * NF + 255) / 256, 256>>>(out);
    // mask: 2,097,152 pixels, 4 per thread
    mask_kernel<<<(BATCH * HW / 4 + 255) / 256, 256>>>(target);
    // fine histograms
    hist_kernel<<<NSLICE * SPLITS, 256>>>(pred, target);
    // reconstruct + loss
    finish_kernel<<<24, 256>>>(out);
}

// round 3
// speedup vs baseline: 4.3911x; 4.3911x over previous
#include <cuda_runtime.h>
#include <cstdint>

// Problem constants: pred/target [8,3,512,512] fp32, output scalar fp32.
#define BATCH   8
#define CHAN    3
#define HW      262144              // 512*512
#define NB      16                  // coarse bins
#define NF      4096                // fine bins
#define NSLICE  48                  // 2 tensors * 8 * 3
#define SPLITS  20
#define CHUNK   13312               // ceil(HW/SPLITS) rounded to 1024

// Packed fine-bin statistic: bits[45:64) = count, bits[0:45) = sum(delta)*2^27,
// delta = x*4096 - j in [0,1). Worst case count = 262144 < 2^19, sumdelta*2^27 < 2^45.
#define CNT_SHIFT 45
#define DELTA_SCALE 134217728.0f    // 2^27
#define DELTA_INV   (1.0f/134217728.0f)

__device__ unsigned long long g_fine[NSLICE][NF];   // 1.5 MB scratch
__device__ unsigned char      g_maskbuf[BATCH * HW];// 2 MB mask bytes
__device__ float              g_w [NB][NF];         // w(c_j, k)
__device__ float              g_wp[NB][NF];         // dw/dx(c_j, k)
__device__ float              g_hist[NSLICE][NB];   // reconstructed coarse hists

// ---------------------------------------------------------------------------
// Kernel 0: zero scratch + output, build Gaussian tables (65536 exps total).
// ---------------------------------------------------------------------------
__global__ void init_kernel(float* __restrict__ out) {
    int tid = blockIdx.x * blockDim.x + threadIdx.x;
    if (tid < NSLICE * NF) {
        ((unsigned long long*)g_fine)[tid] = 0ULL;
    }
    if (tid < NB * NF) {
        int k = tid / NF;
        int j = tid % NF;
        float ck = (float)k / 15.0f;                     // linspace(0,1,16)
        float cj = ((float)j + 0.5f) * (1.0f / (float)NF);
        float d  = cj - ck;
        float w  = expf(-d * d * 128.0f);                // inv_two_sigma2 = 128
        g_w [k][j] = w;
        g_wp[k][j] = -256.0f * d * w;
    }
    if (tid == 0) *out = 0.0f;
}

// ---------------------------------------------------------------------------
// Kernel 1: brightness mask from target.  mask = mean(target, ch) > 0.4
// ---------------------------------------------------------------------------
__global__ __launch_bounds__(256) void mask_kernel(const float* __restrict__ target) {
    int tid = blockIdx.x * blockDim.x + threadIdx.x;
    int p4  = tid * 4;
    if (p4 >= BATCH * HW) return;
    int b = p4 / HW;
    int r = p4 % HW;
    const float* base = target + (size_t)b * CHAN * HW + r;
    float4 t0 = *(const float4*)(base);
    float4 t1 = *(const float4*)(base + HW);
    float4 t2 = *(const float4*)(base + 2 * HW);
    uchar4 m;
    m.x = (unsigned char)(((t0.x + t1.x) + t2.x) / 3.0f > 0.4f);
    m.y = (unsigned char)(((t0.y + t1.y) + t2.y) / 3.0f > 0.4f);
    m.z = (unsigned char)(((t0.z + t1.z) + t2.z) / 3.0f > 0.4f);
    m.w = (unsigned char)(((t0.w + t1.w) + t2.w) / 3.0f > 0.4f);
    *(uchar4*)(g_maskbuf + p4) = m;
}

// ---------------------------------------------------------------------------
// Kernel 2: fine histogram.  One shared 64-bit atomic per masked pixel.
// grid = NSLICE * SPLITS blocks, 256 threads, 32 KB static smem.
// ---------------------------------------------------------------------------
__device__ __forceinline__ void fine_add(unsigned long long* sh, float x, unsigned char m) {
    if (m) {
        float tf = x * (float)NF;
        int j = (int)tf;
        j = min(max(j, 0), NF - 1);
        float dl = tf - (float)j;                        // exact in fp32, in [0,1)
        unsigned long long p = (1ULL << CNT_SHIFT)
                             | (unsigned long long)(unsigned)(dl * DELTA_SCALE);
        atomicAdd(&sh[j], p);
    }
}

__global__ __launch_bounds__(256) void hist_kernel(const float* __restrict__ pred,
                                                   const float* __restrict__ target) {
    __shared__ unsigned long long sh[NF];                // 32 KB
    int s     = blockIdx.x / SPLITS;                     // slice: tensor*24 + b*3 + c
    int chunk = blockIdx.x % SPLITS;
    int t  = s / 24;
    int bc = s % 24;
    int b  = bc / CHAN;

    for (int j = threadIdx.x; j < NF; j += 256) sh[j] = 0ULL;
    __syncthreads();

    const float* src = (t == 0 ? pred : target) + (size_t)bc * HW;
    const unsigned char* mk = g_maskbuf + (size_t)b * HW;

    int start = chunk * CHUNK;
    int end   = min(start + CHUNK, HW);
    for (int i = start + (int)threadIdx.x * 4; i < end; i += 256 * 4) {
        float4 x = *(const float4*)(src + i);
        uchar4 m = *(const uchar4*)(mk + i);
        fine_add(sh, x.x, m.x);
        fine_add(sh, x.y, m.y);
        fine_add(sh, x.z, m.z);
        fine_add(sh, x.w, m.w);
    }
    __syncthreads();

    unsigned long long* gf = g_fine[s];
    for (int j = threadIdx.x; j < NF; j += 256) {
        unsigned long long v = sh[j];
        if (v) atomicAdd(&gf[j], v);
    }
}

// ---------------------------------------------------------------------------
// Kernel 3: reconstruct 16-bin soft histograms from fine stats.
// FP32 throughout (partial sums <= ~6e3, 128 terms/thread: rel err ~1e-6).
// grid = 48 (one block per slice), 512 threads = 16 bins x 32 lanes.
// ---------------------------------------------------------------------------
__global__ __launch_bounds__(512) void reconstruct_kernel() {
    __shared__ float sn [NF];                            // counts
    __shared__ float sdv[NF];                            // sum(x - c_j)

    int s   = blockIdx.x;
    int tid = threadIdx.x;

    const unsigned long long* gf = g_fine[s];
    for (int j = tid; j < NF; j += 512) {
        unsigned long long v = gf[j];
        float n  = (float)(unsigned)(v >> CNT_SHIFT);
        float sd = (float)(v & ((1ULL << CNT_SHIFT) - 1)) * DELTA_INV;
        sn [j] = n;
        sdv[j] = (sd - 0.5f * n) * (1.0f / (float)NF);   // sum(x_i) - n*c_j
    }
    __syncthreads();

    int k    = tid >> 5;                                 // one warp per coarse bin
    int lane = tid & 31;
    const float* wr  = g_w [k];
    const float* wpr = g_wp[k];
    float acc = 0.0f;
    #pragma unroll 4
    for (int j = lane; j < NF; j += 32)
        acc = fmaf(sn[j], wr[j], fmaf(sdv[j], wpr[j], acc));
    #pragma unroll
    for (int off = 16; off > 0; off >>= 1)
        acc += __shfl_xor_sync(0xffffffffu, acc, off);
    if (lane == 0) g_hist[s][k] = acc;
}

// ---------------------------------------------------------------------------
// Kernel 4: normalize + mean |pred_hist - target_hist|.  1 block, 32 threads.
// Deterministic: single shared-memory reduce, one store.
// ---------------------------------------------------------------------------
__global__ __launch_bounds__(32) void final_kernel(float* __restrict__ out) {
    __shared__ double part[32];
    int tid = threadIdx.x;
    double acc = 0.0;
    if (tid < 24) {
        const float* hp = g_hist[tid];                   // pred slice bc
        const float* ht = g_hist[24 + tid];              // target slice bc
        double s0 = 0.0, s1 = 0.0;
        #pragma unroll
        for (int k = 0; k < NB; k++) { s0 += (double)hp[k]; s1 += (double)ht[k]; }
        double i0 = 1.0 / (s0 + 1e-7);
        double i1 = 1.0 / (s1 + 1e-7);
        #pragma unroll
        for (int k = 0; k < NB; k++)
            acc += fabs((double)hp[k] * i0 - (double)ht[k] * i1);
    }
    part[tid] = acc;
    __syncwarp();
    if (tid == 0) {
        double s = 0.0;
        #pragma unroll
        for (int i = 0; i < 24; i++) s += part[i];
        *out = (float)(s * (1.0 / 384.0));
    }
}

// ---------------------------------------------------------------------------
extern "C" void kernel_launch(void* const* d_in, const int* in_sizes, int n_in,
                              void* d_out, int out_size) {
    const float* pred   = (const float*)d_in[0];
    const float* target = (const float*)d_in[1];
    float* out = (float*)d_out;

    init_kernel<<<(NSLICE * NF + 255) / 256, 256>>>(out);
    mask_kernel<<<(BATCH * HW / 4 + 255) / 256, 256>>>(target);
    hist_kernel<<<NSLICE * SPLITS, 256>>>(pred, target);
    reconstruct_kernel<<<NSLICE, 512>>>();
    final_kernel<<<1, 32>>>(out);
}

// round 4
// speedup vs baseline: 11.2936x; 2.5719x over previous
#include <cuda_runtime.h>
#include <cstdint>

// Problem constants: pred/target [8,3,512,512] fp32, output scalar fp32.
#define BATCH   8
#define CHAN    3
#define HW      262144              // 512*512
#define NB      16                  // coarse bins
#define NF      1024                // fine bins
#define NSLICE  48                  // 2 tensors * 8 * 3
#define SPLITS  20
#define CHUNK   13312               // ceil(HW/SPLITS) rounded up

// Per-pixel fixed point: u = (uint)(x * 16384)  (exact: x in [0,1), *2^14 exact)
//   fine bin j = u >> 4   (0..1023),  sub-bin delta16 = u & 15 (delta in units of 1/16 fine bin)
// Smem cell (32-bit): count in bits[18:32), sum(delta16) in bits[0:18).
//   worst case per block: 13312 px -> count <= 13312 < 2^14, sum <= 13312*15 = 199680 < 2^18.
// Global cell (64-bit): count in high 32, sum(delta16) in low 32.
//   worst case per slice: 262144 px -> sum <= 3.9M < 2^32. No cross-field carry possible.

__device__ unsigned long long g_fine[NSLICE][NF];   // 384 KB scratch
__device__ unsigned char      g_maskbuf[BATCH * HW];// 2 MB mask bytes
__device__ float              g_w [NB][NF];         // w(c_j, k)
__device__ float              g_wp[NB][NF];         // dw/dx(c_j, k)
__device__ float              g_hist[NSLICE][NB];   // reconstructed coarse hists
__device__ unsigned int       g_ctr;                // completion ticket

// ---------------------------------------------------------------------------
// Kernel 0 (fused): brightness mask + zero scratch + Gaussian tables.
// grid layout: [0,2048) mask | [2048,2240) zero g_fine | [2240,2304) tables
// ---------------------------------------------------------------------------
#define MASK_BLKS  2048
#define ZERO_BLKS  192
#define TAB_BLKS   64

__global__ __launch_bounds__(256) void init_mask_kernel(const float* __restrict__ target) {
    int blk = blockIdx.x;
    if (blk < MASK_BLKS) {
        int p4 = (blk * 256 + threadIdx.x) * 4;          // exactly covers BATCH*HW
        int b = p4 / HW;
        int r = p4 % HW;
        const float* base = target + (size_t)b * CHAN * HW + r;
        float4 t0 = *(const float4*)(base);
        float4 t1 = *(const float4*)(base + HW);
        float4 t2 = *(const float4*)(base + 2 * HW);
        uchar4 m;
        m.x = (unsigned char)(((t0.x + t1.x) + t2.x) > 1.2f);
        m.y = (unsigned char)(((t0.y + t1.y) + t2.y) > 1.2f);
        m.z = (unsigned char)(((t0.z + t1.z) + t2.z) > 1.2f);
        m.w = (unsigned char)(((t0.w + t1.w) + t2.w) > 1.2f);
        *(uchar4*)(g_maskbuf + p4) = m;
        if (blk == 0 && threadIdx.x == 0) g_ctr = 0u;
    } else if (blk < MASK_BLKS + ZERO_BLKS) {
        int idx = (blk - MASK_BLKS) * 256 + threadIdx.x; // < 49152 = NSLICE*NF
        ((unsigned long long*)g_fine)[idx] = 0ULL;
    } else {
        int idx = (blk - MASK_BLKS - ZERO_BLKS) * 256 + threadIdx.x; // < 16384
        int k = idx >> 10;
        int j = idx & (NF - 1);
        float ck = (float)k / 15.0f;                     // linspace(0,1,16)
        float cj = ((float)j + 0.5f) * (1.0f / (float)NF);
        float d  = cj - ck;
        float w  = expf(-d * d * 128.0f);                // inv_two_sigma2 = 128
        g_w [k][j] = w;
        g_wp[k][j] = -256.0f * d * w;
    }
}

// ---------------------------------------------------------------------------
// Kernel 1: fine histogram.  One 32-bit shared atomic per masked pixel.
// grid = NSLICE * SPLITS blocks, 256 threads, 4 KB smem.
// ---------------------------------------------------------------------------
__device__ __forceinline__ void fine_add(unsigned int* sh, float x, unsigned char m) {
    if (m) {
        unsigned int u = (unsigned int)(x * 16384.0f);   // exact fixed point
        atomicAdd(&sh[u >> 4], 0x40000u | (u & 15u));
    }
}

__global__ __launch_bounds__(256) void hist_kernel(const float* __restrict__ pred,
                                                   const float* __restrict__ target) {
    __shared__ unsigned int sh[NF];                      // 4 KB
    int s     = blockIdx.x / SPLITS;                     // slice: tensor*24 + b*3 + c
    int chunk = blockIdx.x % SPLITS;
    int t  = s / 24;
    int bc = s % 24;
    int b  = bc / CHAN;

    #pragma unroll
    for (int j = threadIdx.x; j < NF; j += 256) sh[j] = 0u;
    __syncthreads();

    const float* src = (t == 0 ? pred : target) + (size_t)bc * HW;
    const unsigned char* mk = g_maskbuf + (size_t)b * HW;

    int start = chunk * CHUNK;
    int end   = min(start + CHUNK, HW);
    for (int i = start + (int)threadIdx.x * 4; i < end; i += 256 * 4) {
        float4 x = *(const float4*)(src + i);
        uchar4 m = *(const uchar4*)(mk + i);
        fine_add(sh, x.x, m.x);
        fine_add(sh, x.y, m.y);
        fine_add(sh, x.z, m.z);
        fine_add(sh, x.w, m.w);
    }
    __syncthreads();

    unsigned long long* gf = g_fine[s];
    #pragma unroll
    for (int j = threadIdx.x; j < NF; j += 256) {
        unsigned int v = sh[j];
        if (v) atomicAdd(&gf[j],
                 ((unsigned long long)(v >> 18) << 32) | (unsigned long long)(v & 0x3FFFFu));
    }
}

// ---------------------------------------------------------------------------
// Kernel 2 (fused): reconstruct 16-bin soft histograms (1st-order Taylor over
// fine bins, delta16 bias-corrected) + last block computes the final loss.
// grid = 48 (one block per slice), 512 threads = 16 bins x 32 lanes.
// ---------------------------------------------------------------------------
__global__ __launch_bounds__(512) void reconstruct_final_kernel(float* __restrict__ out) {
    __shared__ float sn [NF];                            // counts
    __shared__ float sdv[NF];                            // sum(x_i - c_j)
    __shared__ bool  amLast;
    __shared__ double part[24];

    int s   = blockIdx.x;
    int tid = threadIdx.x;

    const unsigned long long* gf = g_fine[s];
    #pragma unroll
    for (int j = tid; j < NF; j += 512) {
        unsigned long long v = gf[j];
        float n  = (float)(unsigned)(v >> 32);
        float sd = (float)(unsigned)(v & 0xFFFFFFFFu);   // sum(delta16)
        sn [j] = n;
        // true sum(delta) ~= (sum(delta16) + 0.5 n)/16 ; sdv = (sum(delta) - n/2) * (1/NF)
        sdv[j] = (sd * 0.0625f - n * 0.46875f) * (1.0f / (float)NF);
    }
    __syncthreads();

    int k    = tid >> 5;                                 // one warp per coarse bin
    int lane = tid & 31;
    const float* wr  = g_w [k];
    const float* wpr = g_wp[k];
    float a0 = 0.0f, a1 = 0.0f;
    #pragma unroll
    for (int j0 = 0; j0 < NF; j0 += 64) {
        int ja = j0 + lane, jb = j0 + 32 + lane;
        a0 = fmaf(sn[ja], __ldg(&wr[ja]), fmaf(sdv[ja], __ldg(&wpr[ja]), a0));
        a1 = fmaf(sn[jb], __ldg(&wr[jb]), fmaf(sdv[jb], __ldg(&wpr[jb]), a1));
    }
    float acc = a0 + a1;
    #pragma unroll
    for (int off = 16; off > 0; off >>= 1)
        acc += __shfl_xor_sync(0xffffffffu, acc, off);
    if (lane == 0) g_hist[s][k] = acc;
    __syncthreads();

    // ticket: last block to finish computes the loss
    if (tid == 0) {
        __threadfence();
        unsigned int t = atomicAdd(&g_ctr, 1u);
        amLast = (t == (unsigned)(gridDim.x - 1));
    }
    __syncthreads();
    if (!amLast) return;

    double acc2 = 0.0;
    if (tid < 24) {
        const float* hp = g_hist[tid];                   // pred slice bc
        const float* ht = g_hist[24 + tid];              // target slice bc
        double s0 = 0.0, s1 = 0.0;
        #pragma unroll
        for (int kk = 0; kk < NB; kk++) { s0 += (double)hp[kk]; s1 += (double)ht[kk]; }
        double i0 = 1.0 / (s0 + 1e-7);
        double i1 = 1.0 / (s1 + 1e-7);
        #pragma unroll
        for (int kk = 0; kk < NB; kk++)
            acc2 += fabs((double)hp[kk] * i0 - (double)ht[kk] * i1);
        part[tid] = acc2;
    }
    __syncthreads();
    if (tid == 0) {
        double ssum = 0.0;
        #pragma unroll
        for (int i = 0; i < 24; i++) ssum += part[i];
        *out = (float)(ssum * (1.0 / 384.0));
    }
}

// ---------------------------------------------------------------------------
extern "C" void kernel_launch(void* const* d_in, const int* in_sizes, int n_in,
                              void* d_out, int out_size) {
    const float* pred   = (const float*)d_in[0];
    const float* target = (const float*)d_in[1];
    float* out = (float*)d_out;

    init_mask_kernel<<<MASK_BLKS + ZERO_BLKS + TAB_BLKS, 256>>>(target);
    hist_kernel<<<NSLICE * SPLITS, 256>>>(pred, target);
    reconstruct_final_kernel<<<NSLICE, 512>>>(out);
}